// round 14
// baseline (speedup 1.0000x reference)
#include <cuda_runtime.h>
#include <cuda_fp16.h>
#include <cstdint>

#define BT  128
#define HH  64
#define GG  192
#define TT  12
#define CC  10
#define NN  325
#define BB  32
#define BNR (BB*NN)
#define NOUT (BNR*TT)

// ---- SMEM byte offsets ----
#define A_T    0u        // h fp16: 128 rows x 128B (SW128 swizzled)
#define W_T    16384u    // Whh fp16: 192 rows x 128B
#define CST_O  40960u    // 64 units x 12 floats {r: w0,w1,bsum,0 | z: w0,w1,bsum,0 | n: w0,w1,bin,bhn}
#define X_O    44032u    // 128 x float2 per-row input (x0,x1)
#define LIN_O  45056u    // 64 floats lin_W + lin_b
#define SMEM_BYTES 45568

// ------------------------- helpers -------------------------
__device__ __forceinline__ uint32_t smem_u32(const void* p) {
    uint32_t a;
    asm("{ .reg .u64 t; cvta.to.shared.u64 t, %1; cvt.u32.u64 %0, t; }"
        : "=r"(a) : "l"(p));
    return a;
}
__device__ __forceinline__ void ldsm4(uint32_t* r, uint32_t addr) {
    asm volatile("ldmatrix.sync.aligned.m8n8.x4.shared.b16 {%0,%1,%2,%3}, [%4];"
                 : "=r"(r[0]), "=r"(r[1]), "=r"(r[2]), "=r"(r[3]) : "r"(addr));
}
// fp16-accumulate HMMA, D/C packed half2 x2
__device__ __forceinline__ void hmma16(uint32_t* d, const uint32_t* a,
                                       uint32_t b0, uint32_t b1) {
    asm volatile(
        "mma.sync.aligned.m16n8k16.row.col.f16.f16.f16.f16 "
        "{%0,%1}, {%2,%3,%4,%5}, {%6,%7}, {%0,%1};"
        : "+r"(d[0]), "+r"(d[1])
        : "r"(a[0]), "r"(a[1]), "r"(a[2]), "r"(a[3]), "r"(b0), "r"(b1));
}
// chain-start HMMA: C = zero (separate from D) -> no acc init MOVs
__device__ __forceinline__ void hmma16_zc(uint32_t* d, const uint32_t* a,
                                          uint32_t b0, uint32_t b1) {
    asm volatile(
        "mma.sync.aligned.m16n8k16.row.col.f16.f16.f16.f16 "
        "{%0,%1}, {%2,%3,%4,%5}, {%6,%7}, {%8,%8};"
        : "=r"(d[0]), "=r"(d[1])
        : "r"(a[0]), "r"(a[1]), "r"(a[2]), "r"(a[3]), "r"(b0), "r"(b1),
          "r"(0u));
}
__device__ __forceinline__ void sts32(uint32_t addr, uint32_t v) {
    asm volatile("st.shared.b32 [%0], %1;" :: "r"(addr), "r"(v) : "memory");
}
__device__ __forceinline__ void sts64f(uint32_t addr, float a, float b) {
    asm volatile("st.shared.v2.f32 [%0], {%1,%2};" :: "r"(addr), "f"(a), "f"(b)
                 : "memory");
}
__device__ __forceinline__ uint32_t lds32(uint32_t addr) {
    uint32_t v;
    asm volatile("ld.shared.b32 %0, [%1];" : "=r"(v) : "r"(addr));
    return v;
}
__device__ __forceinline__ float2 lds64f(uint32_t addr) {
    float2 v;
    asm volatile("ld.shared.v2.f32 {%0,%1}, [%2];"
                 : "=f"(v.x), "=f"(v.y) : "r"(addr));
    return v;
}
__device__ __forceinline__ float4 lds128f(uint32_t addr) {
    float4 v;
    asm volatile("ld.shared.v4.f32 {%0,%1,%2,%3}, [%4];"
                 : "=f"(v.x), "=f"(v.y), "=f"(v.z), "=f"(v.w) : "r"(addr));
    return v;
}
__device__ __forceinline__ uint32_t pack2h(float a, float b) {
    __half2 h2 = __floats2half2_rn(a, b);
    return *(uint32_t*)&h2;
}
__device__ __forceinline__ __half2 u2h(uint32_t v) { return *(__half2*)&v; }

// single-MUFU transcendentals (MUFU.TANH)
__device__ __forceinline__ float tanhx(float x) {
    float y; asm("tanh.approx.f32 %0, %1;" : "=f"(y) : "f"(x)); return y;
}
__device__ __forceinline__ float sigm(float x) {
    return fmaf(0.5f, tanhx(0.5f * x), 0.5f);
}

// stage Whh (192x64 fp32) as a single fp16 SW128-swizzled tile
__device__ __forceinline__ void stage_whh(char* smem, const float* Wc, int tid) {
    for (int idx = tid; idx < GG * HH; idx += BT) {
        int g = idx >> 6, k = idx & 63;
        uint32_t off = (uint32_t)g * 128u + (uint32_t)k * 2u;
        uint32_t sw = off ^ ((off >> 3) & 0x70);
        *(__half*)(smem + W_T + sw) = __float2half_rn(Wc[idx]);
    }
}

// load B tiles for chunk ch, issue 24 fp16-acc HMMA: two independent K-chains
// (kt 0-1 -> aA, kt 2-3 -> aB), each chain started with C = 0
__device__ __forceinline__ void issue_chunk(uint32_t sb, uint32_t bRow,
                                            uint32_t bk0, uint32_t bk1,
                                            const uint32_t (&Ah)[2][4][4],
                                            uint32_t (*aA)[2][2],
                                            uint32_t (*aB)[2][2], int ch) {
    uint32_t B0[3][8];
    #pragma unroll
    for (int g = 0; g < 3; g++) {
        uint32_t wb = sb + W_T + (uint32_t)(g*64 + ch*8) * 128u + bRow;
        ldsm4(&B0[g][0], wb + bk0);
        ldsm4(&B0[g][4], wb + bk1);
    }
    #pragma unroll
    for (int g = 0; g < 3; g++)
        #pragma unroll
        for (int mt = 0; mt < 2; mt++) {
            hmma16_zc(aA[g][mt], Ah[mt][0], B0[g][0], B0[g][1]);
            hmma16   (aA[g][mt], Ah[mt][1], B0[g][2], B0[g][3]);
            hmma16_zc(aB[g][mt], Ah[mt][2], B0[g][4], B0[g][5]);
            hmma16   (aB[g][mt], Ah[mt][3], B0[g][6], B0[g][7]);
        }
}

extern "C" __global__ void __launch_bounds__(BT, 4)
rnn_kernel(const float* __restrict__ X,
           const float* __restrict__ eWih, const float* __restrict__ eWhh,
           const float* __restrict__ ebih, const float* __restrict__ ebhh,
           const float* __restrict__ dWih, const float* __restrict__ dWhh,
           const float* __restrict__ dbih, const float* __restrict__ dbhh,
           const float* __restrict__ linW, const float* __restrict__ linb,
           const float* __restrict__ embed, float* __restrict__ out)
{
    extern __shared__ char smem[];
    const uint32_t sb = smem_u32(smem);
    float* sCst = (float*)(smem + CST_O);
    float* sLin = (float*)(smem + LIN_O);

    const int tid  = threadIdx.x;
    const int lane = tid & 31;
    const int w    = tid >> 5;
    const int l3   = lane & 3;
    const int qr   = lane >> 2;
    const int c    = blockIdx.y;
    const int r    = blockIdx.x * BT + tid;
    const int rr   = (r < BNR) ? r : (BNR - 1);

    // ---- stage encoder weights ----
    stage_whh(smem, eWhh + (size_t)c * GG * HH, tid);
    for (int u = tid; u < HH; u += BT) {
        int base = c * GG;
        sCst[u*12+0]  = eWih[(base + u) * 2 + 0];
        sCst[u*12+1]  = eWih[(base + u) * 2 + 1];
        sCst[u*12+2]  = ebih[base + u] + ebhh[base + u];
        sCst[u*12+3]  = 0.0f;
        sCst[u*12+4]  = eWih[(base + 64 + u) * 2 + 0];
        sCst[u*12+5]  = eWih[(base + 64 + u) * 2 + 1];
        sCst[u*12+6]  = ebih[base + 64 + u] + ebhh[base + 64 + u];
        sCst[u*12+7]  = 0.0f;
        sCst[u*12+8]  = eWih[(base + 128 + u) * 2 + 0];
        sCst[u*12+9]  = eWih[(base + 128 + u) * 2 + 1];
        sCst[u*12+10] = ebih[base + 128 + u];
        sCst[u*12+11] = ebhh[base + 128 + u];
    }
    for (int i = tid; i < 4096; i += BT) ((uint32_t*)(smem + A_T))[i] = 0u;
    __syncthreads();

    // ---- per-lane address constants ----
    const int rb = lane & 15;
    const uint32_t aBase0 = sb + A_T + (uint32_t)(w*32 + rb) * 128u;
    const uint32_t aBase1 = aBase0 + 16u*128u;
    const uint32_t akh  = ((uint32_t)lane >> 4) * 16u;
    const uint32_t axor = ((uint32_t)(rb & 7)) << 4;
    uint32_t akoff[4];
    #pragma unroll
    for (int kt = 0; kt < 4; kt++) akoff[kt] = ((uint32_t)kt*32u + akh) ^ axor;

    const uint32_t bg    = lane & 7;
    const uint32_t bkoff = ((uint32_t)lane >> 3) * 16u;
    const uint32_t bxor  = bg << 4;
    const uint32_t bk0 = (0u  + bkoff) ^ bxor;
    const uint32_t bk1 = (64u + bkoff) ^ bxor;
    const uint32_t bRow = bg * 128u;

    // fragment-row constants: rows i=0..3 -> warp-local row qr + {0,8,16,24}
    uint32_t hbase[4], hsw[4], xaddr[4];
    int growG[4];
    float wq[4];   // softmax(embed[n])[c] for my rows (fused mix weight)
    #pragma unroll
    for (int i = 0; i < 4; i++) {
        int grow = w*32 + (i>>1)*16 + (i&1)*8 + qr;
        growG[i] = blockIdx.x * BT + grow;
        hbase[i] = sb + A_T + (uint32_t)grow * 128u;
        hsw[i]   = ((uint32_t)(grow & 7)) << 4;
        xaddr[i] = sb + X_O + (uint32_t)grow * 8u;
        int gg = (growG[i] < BNR) ? growG[i] : 0;
        const float* e = embed + (gg % NN) * CC;
        float m = e[0];
        #pragma unroll
        for (int cc = 1; cc < CC; cc++) m = fmaxf(m, e[cc]);
        float s = 0.0f;
        #pragma unroll
        for (int cc = 0; cc < CC; cc++) s += __expf(e[cc] - m);
        wq[i] = __fdividef(__expf(e[c] - m), s);
    }
    const uint32_t colb = (uint32_t)(l3 * 4);       // byte offset of unit pair in row
    const uint32_t cstb = sb + CST_O + (uint32_t)(l3 * 2) * 48u;  // + ch*8*48
    const uint32_t linb_a = sb + LIN_O + (uint32_t)(l3 * 2) * 4u;

    const float* xr = X + (size_t)rr * (TT * 2);
    float lb = 0.0f;

    // ---- peeled step t=0: h = 0 -> gh = 0, no MMA at all ----
    {
        float2 xv0 = *(const float2*)(xr);
        sts64f(sb + X_O + (uint32_t)tid * 8u, xv0.x, xv0.y);
        __syncwarp();
        float x0[4], x1[4];
        #pragma unroll
        for (int i = 0; i < 4; i++) {
            float2 xv = lds64f(xaddr[i]);
            x0[i] = xv.x; x1[i] = xv.y;
        }
        #pragma unroll
        for (int ch = 0; ch < 8; ch++) {
            uint32_t cb = cstb + (uint32_t)(ch * 8) * 48u;
            float4 cr0 = lds128f(cb);       float4 cz0 = lds128f(cb + 16);
            float4 cn0 = lds128f(cb + 32);
            float4 cr1 = lds128f(cb + 48);  float4 cz1 = lds128f(cb + 64);
            float4 cn1 = lds128f(cb + 80);
            uint32_t choff = (uint32_t)(ch * 16) + colb;
            #pragma unroll
            for (int i = 0; i < 4; i++) {
                float rg0 = sigm(fmaf(cr0.x, x0[i], fmaf(cr0.y, x1[i], cr0.z)));
                float zg0 = sigm(fmaf(cz0.x, x0[i], fmaf(cz0.y, x1[i], cz0.z)));
                float gi0 = fmaf(cn0.x, x0[i], fmaf(cn0.y, x1[i], cn0.z));
                float ng0 = tanhx(fmaf(rg0, cn0.w, gi0));
                float hn0 = fmaf(zg0, -ng0, ng0);          // h_old = 0

                float rg1 = sigm(fmaf(cr1.x, x0[i], fmaf(cr1.y, x1[i], cr1.z)));
                float zg1 = sigm(fmaf(cz1.x, x0[i], fmaf(cz1.y, x1[i], cz1.z)));
                float gi1 = fmaf(cn1.x, x0[i], fmaf(cn1.y, x1[i], cn1.z));
                float ng1 = tanhx(fmaf(rg1, cn1.w, gi1));
                float hn1 = fmaf(zg1, -ng1, ng1);

                sts32(hbase[i] + (choff ^ hsw[i]), pack2h(hn0, hn1));
            }
        }
    }

    // ---- main loop t = 1 .. 23 ----
    #pragma unroll 1
    for (int t = 1; t < 2 * TT; t++) {
        if (t == TT) {   // restage decoder weights
            __syncthreads();
            stage_whh(smem, dWhh + (size_t)c * GG * HH, tid);
            for (int u = tid; u < HH; u += BT) {
                int base = c * GG;
                sCst[u*12+0]  = dWih[base + u];
                sCst[u*12+1]  = 0.0f;
                sCst[u*12+2]  = dbih[base + u] + dbhh[base + u];
                sCst[u*12+4]  = dWih[base + 64 + u];
                sCst[u*12+5]  = 0.0f;
                sCst[u*12+6]  = dbih[base + 64 + u] + dbhh[base + 64 + u];
                sCst[u*12+8]  = dWih[base + 128 + u];
                sCst[u*12+9]  = 0.0f;
                sCst[u*12+10] = dbih[base + 128 + u];
                sCst[u*12+11] = dbhh[base + 128 + u];
            }
            for (int k = tid; k < HH; k += BT) sLin[k] = linW[c*HH + k];
            __syncthreads();
            lb = linb[c];
        }

        if (t < TT) {    // stage this step's input (own row -> own warp region)
            float2 xv = *(const float2*)(xr + 2*t);
            sts64f(sb + X_O + (uint32_t)tid * 8u, xv.x, xv.y);
        }
        __syncwarp();    // prev-step hn/sX stores + x staging visible

        // load this warp's A fragments (h fp16)
        uint32_t Ah[2][4][4];
        #pragma unroll
        for (int kt = 0; kt < 4; kt++) {
            ldsm4(Ah[0][kt], aBase0 + akoff[kt]);
            ldsm4(Ah[1][kt], aBase1 + akoff[kt]);
        }

        // per-row inputs
        float x0[4], x1[4], v[4];
        #pragma unroll
        for (int i = 0; i < 4; i++) {
            float2 xv = lds64f(xaddr[i]);
            x0[i] = xv.x;
            x1[i] = (t < TT) ? xv.y : 0.0f;
            v[i] = 0.0f;
        }

        // ---- software-pipelined chunk loop (fp16-acc, double-buffered) ----
        uint32_t accA[2][3][2][2], accB[2][3][2][2];
        issue_chunk(sb, bRow, bk0, bk1, Ah, accA[0], accB[0], 0);

        #pragma unroll
        for (int ch = 0; ch < 8; ch++) {
            if (ch < 7)
                issue_chunk(sb, bRow, bk0, bk1, Ah,
                            accA[(ch + 1) & 1], accB[(ch + 1) & 1], ch + 1);
            uint32_t (*aA)[2][2] = accA[ch & 1];
            uint32_t (*aB)[2][2] = accB[ch & 1];

            // per-unit-pair constants (broadcast across row groups)
            uint32_t cb = cstb + (uint32_t)(ch * 8) * 48u;
            float4 cr0 = lds128f(cb);       float4 cz0 = lds128f(cb + 16);
            float4 cn0 = lds128f(cb + 32);
            float4 cr1 = lds128f(cb + 48);  float4 cz1 = lds128f(cb + 64);
            float4 cn1 = lds128f(cb + 80);
            float2 lw  = lds64f(linb_a + (uint32_t)(ch * 32));

            uint32_t choff = (uint32_t)(ch * 16) + colb;

            #pragma unroll
            for (int i = 0; i < 4; i++) {
                const int mt = i >> 1, p = i & 1;
                // combine the two fp16 K-chains, convert once to fp32
                float2 grf = __half22float2(__hadd2(u2h(aA[0][mt][p]), u2h(aB[0][mt][p])));
                float2 gzf = __half22float2(__hadd2(u2h(aA[1][mt][p]), u2h(aB[1][mt][p])));
                float2 gnf = __half22float2(__hadd2(u2h(aA[2][mt][p]), u2h(aB[2][mt][p])));

                uint32_t haddr = hbase[i] + (choff ^ hsw[i]);
                uint32_t hraw = lds32(haddr);
                float2 ho = __half22float2(*(__half2*)&hraw);

                float rg0 = sigm(grf.x + fmaf(cr0.x, x0[i], fmaf(cr0.y, x1[i], cr0.z)));
                float zg0 = sigm(gzf.x + fmaf(cz0.x, x0[i], fmaf(cz0.y, x1[i], cz0.z)));
                float gi0 = fmaf(cn0.x, x0[i], fmaf(cn0.y, x1[i], cn0.z));
                float ng0 = tanhx(fmaf(rg0, gnf.x + cn0.w, gi0));
                float hn0 = fmaf(zg0, ho.x - ng0, ng0);

                float rg1 = sigm(grf.y + fmaf(cr1.x, x0[i], fmaf(cr1.y, x1[i], cr1.z)));
                float zg1 = sigm(gzf.y + fmaf(cz1.x, x0[i], fmaf(cz1.y, x1[i], cz1.z)));
                float gi1 = fmaf(cn1.x, x0[i], fmaf(cn1.y, x1[i], cn1.z));
                float ng1 = tanhx(fmaf(rg1, gnf.y + cn1.w, gi1));
                float hn1 = fmaf(zg1, ho.y - ng1, ng1);

                sts32(haddr, pack2h(hn0, hn1));

                if (t >= TT)
                    v[i] = fmaf(hn0, lw.x, fmaf(hn1, lw.y, v[i]));
            }
        }

        if (t >= TT) {   // decoder: reduce lin projection, mix-fused output, feed back
            const int td = t - TT;
            #pragma unroll
            for (int i = 0; i < 4; i++) {
                v[i] += __shfl_xor_sync(0xFFFFFFFFu, v[i], 1);
                v[i] += __shfl_xor_sync(0xFFFFFFFFu, v[i], 2);
            }
            if (l3 == 0) {
                #pragma unroll
                for (int i = 0; i < 4; i++) {
                    float val = v[i] + lb;
                    if (growG[i] < BNR)
                        atomicAdd(out + growG[i] * TT + td, wq[i] * val);
                    sts64f(xaddr[i], val, 0.0f);
                }
            }
        }
    }
}

// zero the output (harness poisons it to 0xAA; atomics accumulate into it)
extern "C" __global__ void zero_kernel(float* __restrict__ out)
{
    int i = blockIdx.x * blockDim.x + threadIdx.x;
    if (i < NOUT) out[i] = 0.0f;
}

extern "C" void kernel_launch(void* const* d_in, const int* in_sizes, int n_in,
                              void* d_out, int out_size)
{
    // metadata order: A, X, enc_Wih, enc_Whh, enc_bih, enc_bhh,
    //                 dec_Wih, dec_Whh, dec_bih, dec_bhh, lin_W, lin_b, embed
    const float* X     = (const float*)d_in[1];
    const float* eWih  = (const float*)d_in[2];
    const float* eWhh  = (const float*)d_in[3];
    const float* ebih  = (const float*)d_in[4];
    const float* ebhh  = (const float*)d_in[5];
    const float* dWih  = (const float*)d_in[6];
    const float* dWhh  = (const float*)d_in[7];
    const float* dbih  = (const float*)d_in[8];
    const float* dbhh  = (const float*)d_in[9];
    const float* linW  = (const float*)d_in[10];
    const float* linb  = (const float*)d_in[11];
    const float* embed = (const float*)d_in[12];
    float* out = (float*)d_out;

    cudaFuncSetAttribute((const void*)rnn_kernel,
                         cudaFuncAttributeMaxDynamicSharedMemorySize, SMEM_BYTES);

    zero_kernel<<<(NOUT + 255) / 256, 256>>>(out);

    dim3 grid((BNR + BT - 1) / BT, CC);   // (82, 10)
    rnn_kernel<<<grid, BT, SMEM_BYTES>>>(X, eWih, eWhh, ebih, ebhh,
                                         dWih, dWhh, dbih, dbhh, linW, linb,
                                         embed, out);
}

// round 15
// speedup vs baseline: 1.0849x; 1.0849x over previous
#include <cuda_runtime.h>
#include <cuda_fp16.h>
#include <cstdint>

#define BT  128
#define HH  64
#define GG  192
#define TT  12
#define CC  10
#define NN  325
#define BB  32
#define BNR (BB*NN)
#define NOUT (BNR*TT)

// ---- SMEM byte offsets ----
#define A_T    0u        // h fp16: 128 rows x 128B (SW128 swizzled)
#define W_T    16384u    // Whh fp16: 192 rows x 128B (r/z rows prescaled x0.5)
#define CST_O  40960u    // 64 units x 12 floats {r: w0,w1,bsum,0 | z: w0,w1,bsum,0 | n: w0,w1,bin,bhn}
#define X_O    44032u    // 128 x float2 per-row input (x0,x1)
#define LIN_O  45056u    // 64 floats lin_W + lin_b
#define SMEM_BYTES 45568

// ------------------------- helpers -------------------------
__device__ __forceinline__ uint32_t smem_u32(const void* p) {
    uint32_t a;
    asm("{ .reg .u64 t; cvta.to.shared.u64 t, %1; cvt.u32.u64 %0, t; }"
        : "=r"(a) : "l"(p));
    return a;
}
__device__ __forceinline__ void ldsm4(uint32_t* r, uint32_t addr) {
    asm volatile("ldmatrix.sync.aligned.m8n8.x4.shared.b16 {%0,%1,%2,%3}, [%4];"
                 : "=r"(r[0]), "=r"(r[1]), "=r"(r[2]), "=r"(r[3]) : "r"(addr));
}
__device__ __forceinline__ void hmma(float* d, const uint32_t* a,
                                     uint32_t b0, uint32_t b1) {
    asm volatile(
        "mma.sync.aligned.m16n8k16.row.col.f32.f16.f16.f32 "
        "{%0,%1,%2,%3}, {%4,%5,%6,%7}, {%8,%9}, {%0,%1,%2,%3};"
        : "+f"(d[0]), "+f"(d[1]), "+f"(d[2]), "+f"(d[3])
        : "r"(a[0]), "r"(a[1]), "r"(a[2]), "r"(a[3]), "r"(b0), "r"(b1));
}
// first-k HMMA: C = zero quad (separate from D) -> no acc zero-init MOVs
__device__ __forceinline__ void hmma_zc(float* d, const uint32_t* a,
                                        uint32_t b0, uint32_t b1,
                                        const float* z) {
    asm volatile(
        "mma.sync.aligned.m16n8k16.row.col.f32.f16.f16.f32 "
        "{%0,%1,%2,%3}, {%4,%5,%6,%7}, {%8,%9}, {%10,%11,%12,%13};"
        : "=f"(d[0]), "=f"(d[1]), "=f"(d[2]), "=f"(d[3])
        : "r"(a[0]), "r"(a[1]), "r"(a[2]), "r"(a[3]), "r"(b0), "r"(b1),
          "f"(z[0]), "f"(z[1]), "f"(z[2]), "f"(z[3]));
}
__device__ __forceinline__ void sts32(uint32_t addr, uint32_t v) {
    asm volatile("st.shared.b32 [%0], %1;" :: "r"(addr), "r"(v) : "memory");
}
__device__ __forceinline__ void sts64f(uint32_t addr, float a, float b) {
    asm volatile("st.shared.v2.f32 [%0], {%1,%2};" :: "r"(addr), "f"(a), "f"(b)
                 : "memory");
}
__device__ __forceinline__ uint32_t lds32(uint32_t addr) {
    uint32_t v;
    asm volatile("ld.shared.b32 %0, [%1];" : "=r"(v) : "r"(addr));
    return v;
}
__device__ __forceinline__ float2 lds64f(uint32_t addr) {
    float2 v;
    asm volatile("ld.shared.v2.f32 {%0,%1}, [%2];"
                 : "=f"(v.x), "=f"(v.y) : "r"(addr));
    return v;
}
__device__ __forceinline__ float4 lds128f(uint32_t addr) {
    float4 v;
    asm volatile("ld.shared.v4.f32 {%0,%1,%2,%3}, [%4];"
                 : "=f"(v.x), "=f"(v.y), "=f"(v.z), "=f"(v.w) : "r"(addr));
    return v;
}
__device__ __forceinline__ uint32_t pack2h(float a, float b) {
    __half2 h2 = __floats2half2_rn(a, b);
    return *(uint32_t*)&h2;
}
__device__ __forceinline__ __half2 u2h(uint32_t v) { return *(__half2*)&v; }

// pack two f32 into f16x2: lo = first arg, hi = second arg
__device__ __forceinline__ uint32_t packf2h2(float lo, float hi) {
    uint32_t d;
    asm("cvt.rn.f16x2.f32 %0, %1, %2;" : "=r"(d) : "f"(hi), "f"(lo));
    return d;
}
// dual-gate tanh: one MUFU for two values
__device__ __forceinline__ uint32_t tanh2(uint32_t a) {
    uint32_t d;
    asm("tanh.approx.f16x2 %0, %1;" : "=r"(d) : "r"(a));
    return d;
}
// sigmoid pair from PRE-SCALED args (arg = 0.5*logit): 0.5*tanh(arg)+0.5
__device__ __forceinline__ float2 sigm2_s(float a0, float a1) {
    const __half2 h05 = __floats2half2_rn(0.5f, 0.5f);
    __half2 t = u2h(tanh2(packf2h2(a0, a1)));
    return __half22float2(__hfma2(t, h05, h05));
}

// single-MUFU fp32 transcendentals (MUFU.TANH)
__device__ __forceinline__ float tanhx(float x) {
    float y; asm("tanh.approx.f32 %0, %1;" : "=f"(y) : "f"(x)); return y;
}
// fp32 sigmoid from PRE-SCALED arg (peel path)
__device__ __forceinline__ float sigm_s(float x) {
    return fmaf(0.5f, tanhx(x), 0.5f);
}

// stage Whh (192x64 fp32) as fp16 SW128 tile; r/z gate rows (g < 128)
// prescaled by 0.5 (exact in fp16) so sigmoid args arrive pre-scaled
__device__ __forceinline__ void stage_whh(char* smem, const float* Wc, int tid) {
    for (int idx = tid; idx < GG * HH; idx += BT) {
        int g = idx >> 6, k = idx & 63;
        float w = Wc[idx];
        if (g < 128) w *= 0.5f;
        uint32_t off = (uint32_t)g * 128u + (uint32_t)k * 2u;
        uint32_t sw = off ^ ((off >> 3) & 0x70);
        *(__half*)(smem + W_T + sw) = __float2half_rn(w);
    }
}

// load B tiles for chunk ch and issue its 24 HMMA into acc (first kt: C=zero)
__device__ __forceinline__ void issue_chunk(uint32_t sb, uint32_t bRow,
                                            uint32_t bk0, uint32_t bk1,
                                            const uint32_t (&Ah)[2][4][4],
                                            float (*acc)[2][4], int ch,
                                            const float (&zq)[4]) {
    uint32_t B0[3][8];
    #pragma unroll
    for (int g = 0; g < 3; g++) {
        uint32_t wb = sb + W_T + (uint32_t)(g*64 + ch*8) * 128u + bRow;
        ldsm4(&B0[g][0], wb + bk0);
        ldsm4(&B0[g][4], wb + bk1);
    }
    #pragma unroll
    for (int g = 0; g < 3; g++)
        #pragma unroll
        for (int mt = 0; mt < 2; mt++) {
            hmma_zc(acc[g][mt], Ah[mt][0], B0[g][0], B0[g][1], zq);
            #pragma unroll
            for (int kt = 1; kt < 4; kt++) {
                int bi = (kt >> 1) * 4 + (kt & 1) * 2;
                hmma(acc[g][mt], Ah[mt][kt], B0[g][bi], B0[g][bi + 1]);
            }
        }
}

extern "C" __global__ void __launch_bounds__(BT, 3)
rnn_kernel(const float* __restrict__ X,
           const float* __restrict__ eWih, const float* __restrict__ eWhh,
           const float* __restrict__ ebih, const float* __restrict__ ebhh,
           const float* __restrict__ dWih, const float* __restrict__ dWhh,
           const float* __restrict__ dbih, const float* __restrict__ dbhh,
           const float* __restrict__ linW, const float* __restrict__ linb,
           const float* __restrict__ embed, float* __restrict__ out)
{
    extern __shared__ char smem[];
    const uint32_t sb = smem_u32(smem);
    float* sCst = (float*)(smem + CST_O);
    float* sLin = (float*)(smem + LIN_O);

    const int tid  = threadIdx.x;
    const int lane = tid & 31;
    const int w    = tid >> 5;
    const int l3   = lane & 3;
    const int qr   = lane >> 2;
    const int c    = blockIdx.y;
    const int r    = blockIdx.x * BT + tid;
    const int rr   = (r < BNR) ? r : (BNR - 1);

    // ---- stage encoder weights (r/z prescaled by 0.5) ----
    stage_whh(smem, eWhh + (size_t)c * GG * HH, tid);
    for (int u = tid; u < HH; u += BT) {
        int base = c * GG;
        sCst[u*12+0]  = 0.5f * eWih[(base + u) * 2 + 0];
        sCst[u*12+1]  = 0.5f * eWih[(base + u) * 2 + 1];
        sCst[u*12+2]  = 0.5f * (ebih[base + u] + ebhh[base + u]);
        sCst[u*12+3]  = 0.0f;
        sCst[u*12+4]  = 0.5f * eWih[(base + 64 + u) * 2 + 0];
        sCst[u*12+5]  = 0.5f * eWih[(base + 64 + u) * 2 + 1];
        sCst[u*12+6]  = 0.5f * (ebih[base + 64 + u] + ebhh[base + 64 + u]);
        sCst[u*12+7]  = 0.0f;
        sCst[u*12+8]  = eWih[(base + 128 + u) * 2 + 0];
        sCst[u*12+9]  = eWih[(base + 128 + u) * 2 + 1];
        sCst[u*12+10] = ebih[base + 128 + u];
        sCst[u*12+11] = ebhh[base + 128 + u];
    }
    for (int i = tid; i < 4096; i += BT) ((uint32_t*)(smem + A_T))[i] = 0u;
    __syncthreads();

    // ---- per-lane address constants ----
    const int rb = lane & 15;
    const uint32_t aBase0 = sb + A_T + (uint32_t)(w*32 + rb) * 128u;
    const uint32_t aBase1 = aBase0 + 16u*128u;
    const uint32_t akh  = ((uint32_t)lane >> 4) * 16u;
    const uint32_t axor = ((uint32_t)(rb & 7)) << 4;
    uint32_t akoff[4];
    #pragma unroll
    for (int kt = 0; kt < 4; kt++) akoff[kt] = ((uint32_t)kt*32u + akh) ^ axor;

    const uint32_t bg    = lane & 7;
    const uint32_t bkoff = ((uint32_t)lane >> 3) * 16u;
    const uint32_t bxor  = bg << 4;
    const uint32_t bk0 = (0u  + bkoff) ^ bxor;
    const uint32_t bk1 = (64u + bkoff) ^ bxor;
    const uint32_t bRow = bg * 128u;

    // fragment-row constants: rows i=0..3 -> warp-local row qr + {0,8,16,24}
    uint32_t hbase[4], hsw[4], xaddr[4];
    int growG[4];
    float wq[4];   // softmax(embed[n])[c] for my rows (fused mix weight)
    #pragma unroll
    for (int i = 0; i < 4; i++) {
        int grow = w*32 + (i>>1)*16 + (i&1)*8 + qr;
        growG[i] = blockIdx.x * BT + grow;
        hbase[i] = sb + A_T + (uint32_t)grow * 128u;
        hsw[i]   = ((uint32_t)(grow & 7)) << 4;
        xaddr[i] = sb + X_O + (uint32_t)grow * 8u;
        int gg = (growG[i] < BNR) ? growG[i] : 0;
        const float* e = embed + (gg % NN) * CC;
        float m = e[0];
        #pragma unroll
        for (int cc = 1; cc < CC; cc++) m = fmaxf(m, e[cc]);
        float s = 0.0f;
        #pragma unroll
        for (int cc = 0; cc < CC; cc++) s += __expf(e[cc] - m);
        wq[i] = __fdividef(__expf(e[c] - m), s);
    }
    const uint32_t colb = (uint32_t)(l3 * 4);       // byte offset of unit pair in row
    const uint32_t cstb = sb + CST_O + (uint32_t)(l3 * 2) * 48u;  // + ch*8*48
    const uint32_t linb_a = sb + LIN_O + (uint32_t)(l3 * 2) * 4u;

    const float* xr = X + (size_t)rr * (TT * 2);
    float lb = 0.0f;

    // zero quad for first-k HMMA C operand
    float zq[4] = {0.0f, 0.0f, 0.0f, 0.0f};

    // ---- peeled step t=0: h = 0 -> gh = 0, no MMA at all ----
    {
        float2 xv0 = *(const float2*)(xr);
        sts64f(sb + X_O + (uint32_t)tid * 8u, xv0.x, xv0.y);
        __syncwarp();
        float x0[4], x1[4];
        #pragma unroll
        for (int i = 0; i < 4; i++) {
            float2 xv = lds64f(xaddr[i]);
            x0[i] = xv.x; x1[i] = xv.y;
        }
        #pragma unroll
        for (int ch = 0; ch < 8; ch++) {
            uint32_t cb = cstb + (uint32_t)(ch * 8) * 48u;
            float4 cr0 = lds128f(cb);       float4 cz0 = lds128f(cb + 16);
            float4 cn0 = lds128f(cb + 32);
            float4 cr1 = lds128f(cb + 48);  float4 cz1 = lds128f(cb + 64);
            float4 cn1 = lds128f(cb + 80);
            uint32_t choff = (uint32_t)(ch * 16) + colb;
            #pragma unroll
            for (int i = 0; i < 4; i++) {
                float rg0 = sigm_s(fmaf(cr0.x, x0[i], fmaf(cr0.y, x1[i], cr0.z)));
                float zg0 = sigm_s(fmaf(cz0.x, x0[i], fmaf(cz0.y, x1[i], cz0.z)));
                float gi0 = fmaf(cn0.x, x0[i], fmaf(cn0.y, x1[i], cn0.z));
                float ng0 = tanhx(fmaf(rg0, cn0.w, gi0));
                float hn0 = fmaf(zg0, -ng0, ng0);          // h_old = 0

                float rg1 = sigm_s(fmaf(cr1.x, x0[i], fmaf(cr1.y, x1[i], cr1.z)));
                float zg1 = sigm_s(fmaf(cz1.x, x0[i], fmaf(cz1.y, x1[i], cz1.z)));
                float gi1 = fmaf(cn1.x, x0[i], fmaf(cn1.y, x1[i], cn1.z));
                float ng1 = tanhx(fmaf(rg1, cn1.w, gi1));
                float hn1 = fmaf(zg1, -ng1, ng1);

                sts32(hbase[i] + (choff ^ hsw[i]), pack2h(hn0, hn1));
            }
        }
    }

    // ---- main loop t = 1 .. 23 ----
    #pragma unroll 1
    for (int t = 1; t < 2 * TT; t++) {
        if (t == TT) {   // restage decoder weights (r/z prescaled by 0.5)
            __syncthreads();
            stage_whh(smem, dWhh + (size_t)c * GG * HH, tid);
            for (int u = tid; u < HH; u += BT) {
                int base = c * GG;
                sCst[u*12+0]  = 0.5f * dWih[base + u];
                sCst[u*12+1]  = 0.0f;
                sCst[u*12+2]  = 0.5f * (dbih[base + u] + dbhh[base + u]);
                sCst[u*12+4]  = 0.5f * dWih[base + 64 + u];
                sCst[u*12+5]  = 0.0f;
                sCst[u*12+6]  = 0.5f * (dbih[base + 64 + u] + dbhh[base + 64 + u]);
                sCst[u*12+8]  = dWih[base + 128 + u];
                sCst[u*12+9]  = 0.0f;
                sCst[u*12+10] = dbih[base + 128 + u];
                sCst[u*12+11] = dbhh[base + 128 + u];
            }
            for (int k = tid; k < HH; k += BT) sLin[k] = linW[c*HH + k];
            __syncthreads();
            lb = linb[c];
        }

        if (t < TT) {    // stage this step's input (own row -> own warp region)
            float2 xv = *(const float2*)(xr + 2*t);
            sts64f(sb + X_O + (uint32_t)tid * 8u, xv.x, xv.y);
        }
        __syncwarp();    // prev-step hn/sX stores + x staging visible

        // load this warp's A fragments (h fp16)
        uint32_t Ah[2][4][4];
        #pragma unroll
        for (int kt = 0; kt < 4; kt++) {
            ldsm4(Ah[0][kt], aBase0 + akoff[kt]);
            ldsm4(Ah[1][kt], aBase1 + akoff[kt]);
        }

        // per-row inputs
        float x0[4], x1[4], v[4];
        #pragma unroll
        for (int i = 0; i < 4; i++) {
            float2 xv = lds64f(xaddr[i]);
            x0[i] = xv.x;
            x1[i] = (t < TT) ? xv.y : 0.0f;
            v[i] = 0.0f;
        }

        // ---- software-pipelined chunk loop ----
        float accbuf[2][3][2][4];
        issue_chunk(sb, bRow, bk0, bk1, Ah, accbuf[0], 0, zq);

        #pragma unroll
        for (int ch = 0; ch < 8; ch++) {
            if (ch < 7)
                issue_chunk(sb, bRow, bk0, bk1, Ah, accbuf[(ch + 1) & 1], ch + 1, zq);
            float (*acc)[2][4] = accbuf[ch & 1];

            // per-unit-pair constants (broadcast across row groups)
            uint32_t cb = cstb + (uint32_t)(ch * 8) * 48u;
            float4 cr0 = lds128f(cb);       float4 cz0 = lds128f(cb + 16);
            float4 cn0 = lds128f(cb + 32);
            float4 cr1 = lds128f(cb + 48);  float4 cz1 = lds128f(cb + 64);
            float4 cn1 = lds128f(cb + 80);
            float2 lw  = lds64f(linb_a + (uint32_t)(ch * 32));

            uint32_t choff = (uint32_t)(ch * 16) + colb;

            #pragma unroll
            for (int i = 0; i < 4; i++) {
                const int mt = i >> 1, p = i & 1;
                float gr0 = acc[0][mt][2*p],   gr1 = acc[0][mt][2*p+1];
                float gz0 = acc[1][mt][2*p],   gz1 = acc[1][mt][2*p+1];
                float gn0 = acc[2][mt][2*p],   gn1 = acc[2][mt][2*p+1];

                uint32_t haddr = hbase[i] + (choff ^ hsw[i]);
                uint32_t hraw = lds32(haddr);
                float2 ho = __half22float2(*(__half2*)&hraw);

                // r/z: args arrive pre-scaled (W & cst x0.5); dual-gate f16x2 tanh
                float ar0 = gr0 + fmaf(cr0.x, x0[i], fmaf(cr0.y, x1[i], cr0.z));
                float ar1 = gr1 + fmaf(cr1.x, x0[i], fmaf(cr1.y, x1[i], cr1.z));
                float az0 = gz0 + fmaf(cz0.x, x0[i], fmaf(cz0.y, x1[i], cz0.z));
                float az1 = gz1 + fmaf(cz1.x, x0[i], fmaf(cz1.y, x1[i], cz1.z));
                float2 rgf = sigm2_s(ar0, ar1);
                float2 zgf = sigm2_s(az0, az1);

                float gi0 = fmaf(cn0.x, x0[i], fmaf(cn0.y, x1[i], cn0.z));
                float ng0 = tanhx(fmaf(rgf.x, gn0 + cn0.w, gi0));
                float hn0 = fmaf(zgf.x, ho.x - ng0, ng0);

                float gi1 = fmaf(cn1.x, x0[i], fmaf(cn1.y, x1[i], cn1.z));
                float ng1 = tanhx(fmaf(rgf.y, gn1 + cn1.w, gi1));
                float hn1 = fmaf(zgf.y, ho.y - ng1, ng1);

                sts32(haddr, pack2h(hn0, hn1));

                if (t >= TT)
                    v[i] = fmaf(hn0, lw.x, fmaf(hn1, lw.y, v[i]));
            }
        }

        if (t >= TT) {   // decoder: reduce lin projection, mix-fused output, feed back
            const int td = t - TT;
            #pragma unroll
            for (int i = 0; i < 4; i++) {
                v[i] += __shfl_xor_sync(0xFFFFFFFFu, v[i], 1);
                v[i] += __shfl_xor_sync(0xFFFFFFFFu, v[i], 2);
            }
            if (l3 == 0) {
                #pragma unroll
                for (int i = 0; i < 4; i++) {
                    float val = v[i] + lb;
                    if (growG[i] < BNR)
                        atomicAdd(out + growG[i] * TT + td, wq[i] * val);
                    sts64f(xaddr[i], val, 0.0f);
                }
            }
        }
    }
}

// zero the output (harness poisons it to 0xAA; atomics accumulate into it)
extern "C" __global__ void zero_kernel(float* __restrict__ out)
{
    int i = blockIdx.x * blockDim.x + threadIdx.x;
    if (i < NOUT) out[i] = 0.0f;
}

extern "C" void kernel_launch(void* const* d_in, const int* in_sizes, int n_in,
                              void* d_out, int out_size)
{
    // metadata order: A, X, enc_Wih, enc_Whh, enc_bih, enc_bhh,
    //                 dec_Wih, dec_Whh, dec_bih, dec_bhh, lin_W, lin_b, embed
    const float* X     = (const float*)d_in[1];
    const float* eWih  = (const float*)d_in[2];
    const float* eWhh  = (const float*)d_in[3];
    const float* ebih  = (const float*)d_in[4];
    const float* ebhh  = (const float*)d_in[5];
    const float* dWih  = (const float*)d_in[6];
    const float* dWhh  = (const float*)d_in[7];
    const float* dbih  = (const float*)d_in[8];
    const float* dbhh  = (const float*)d_in[9];
    const float* linW  = (const float*)d_in[10];
    const float* linb  = (const float*)d_in[11];
    const float* embed = (const float*)d_in[12];
    float* out = (float*)d_out;

    cudaFuncSetAttribute((const void*)rnn_kernel,
                         cudaFuncAttributeMaxDynamicSharedMemorySize, SMEM_BYTES);

    zero_kernel<<<(NOUT + 255) / 256, 256>>>(out);

    dim3 grid((BNR + BT - 1) / BT, CC);   // (82, 10)
    rnn_kernel<<<grid, BT, SMEM_BYTES>>>(X, eWih, eWhh, ebih, ebhh,
                                         dWih, dWhh, dbih, dbhh, linW, linb,
                                         embed, out);
}

// round 17
// speedup vs baseline: 1.1386x; 1.0495x over previous
#include <cuda_runtime.h>
#include <cuda_fp16.h>
#include <cstdint>

#define BT  128
#define HH  64
#define GG  192
#define TT  12
#define CC  10
#define NN  325
#define BB  32
#define BNR (BB*NN)
#define NOUT (BNR*TT)

// ---- SMEM byte offsets ----
#define A_T    0u        // h fp16: 128 rows x 128B (SW128 swizzled)
#define W_T    16384u    // Whh fp16: 192 rows x 128B (r/z rows prescaled x0.5)
#define CST_O  40960u    // 64 units x 12 floats (full set kept for peel; main loop reads n-part only)
#define X_O    44032u    // 128 x float2 per-row input (x0,x1)
#define LIN_O  45056u    // 64 floats lin_W
#define A2_O   45568u    // augmented A: 128 rows x 48B  [x0,x1,1,0...] fp16
#define W2_O   51712u    // augmented W: 128 rows (r,z) x 48B  [.5wih0,.5wih1,.5bsum,0...]
#define SMEM_BYTES 57856

// ------------------------- helpers -------------------------
__device__ __forceinline__ uint32_t smem_u32(const void* p) {
    uint32_t a;
    asm("{ .reg .u64 t; cvta.to.shared.u64 t, %1; cvt.u32.u64 %0, t; }"
        : "=r"(a) : "l"(p));
    return a;
}
__device__ __forceinline__ void ldsm4(uint32_t* r, uint32_t addr) {
    asm volatile("ldmatrix.sync.aligned.m8n8.x4.shared.b16 {%0,%1,%2,%3}, [%4];"
                 : "=r"(r[0]), "=r"(r[1]), "=r"(r[2]), "=r"(r[3]) : "r"(addr));
}
__device__ __forceinline__ void ldsm2(uint32_t* r, uint32_t addr) {
    asm volatile("ldmatrix.sync.aligned.m8n8.x2.shared.b16 {%0,%1}, [%2];"
                 : "=r"(r[0]), "=r"(r[1]) : "r"(addr));
}
__device__ __forceinline__ void hmma(float* d, const uint32_t* a,
                                     uint32_t b0, uint32_t b1) {
    asm volatile(
        "mma.sync.aligned.m16n8k16.row.col.f32.f16.f16.f32 "
        "{%0,%1,%2,%3}, {%4,%5,%6,%7}, {%8,%9}, {%0,%1,%2,%3};"
        : "+f"(d[0]), "+f"(d[1]), "+f"(d[2]), "+f"(d[3])
        : "r"(a[0]), "r"(a[1]), "r"(a[2]), "r"(a[3]), "r"(b0), "r"(b1));
}
// first-k HMMA: C = zero quad (separate from D) -> no acc zero-init MOVs
__device__ __forceinline__ void hmma_zc(float* d, const uint32_t* a,
                                        uint32_t b0, uint32_t b1,
                                        const float* z) {
    asm volatile(
        "mma.sync.aligned.m16n8k16.row.col.f32.f16.f16.f32 "
        "{%0,%1,%2,%3}, {%4,%5,%6,%7}, {%8,%9}, {%10,%11,%12,%13};"
        : "=f"(d[0]), "=f"(d[1]), "=f"(d[2]), "=f"(d[3])
        : "r"(a[0]), "r"(a[1]), "r"(a[2]), "r"(a[3]), "r"(b0), "r"(b1),
          "f"(z[0]), "f"(z[1]), "f"(z[2]), "f"(z[3]));
}
__device__ __forceinline__ void sts32(uint32_t addr, uint32_t v) {
    asm volatile("st.shared.b32 [%0], %1;" :: "r"(addr), "r"(v) : "memory");
}
__device__ __forceinline__ void sts64f(uint32_t addr, float a, float b) {
    asm volatile("st.shared.v2.f32 [%0], {%1,%2};" :: "r"(addr), "f"(a), "f"(b)
                 : "memory");
}
__device__ __forceinline__ uint32_t lds32(uint32_t addr) {
    uint32_t v;
    asm volatile("ld.shared.b32 %0, [%1];" : "=r"(v) : "r"(addr));
    return v;
}
__device__ __forceinline__ float2 lds64f(uint32_t addr) {
    float2 v;
    asm volatile("ld.shared.v2.f32 {%0,%1}, [%2];"
                 : "=f"(v.x), "=f"(v.y) : "r"(addr));
    return v;
}
__device__ __forceinline__ float4 lds128f(uint32_t addr) {
    float4 v;
    asm volatile("ld.shared.v4.f32 {%0,%1,%2,%3}, [%4];"
                 : "=f"(v.x), "=f"(v.y), "=f"(v.z), "=f"(v.w) : "r"(addr));
    return v;
}
__device__ __forceinline__ uint32_t pack2h(float a, float b) {
    __half2 h2 = __floats2half2_rn(a, b);
    return *(uint32_t*)&h2;
}
__device__ __forceinline__ __half2 u2h(uint32_t v) { return *(__half2*)&v; }

// pack two f32 into f16x2: lo = first arg, hi = second arg
__device__ __forceinline__ uint32_t packf2h2(float lo, float hi) {
    uint32_t d;
    asm("cvt.rn.f16x2.f32 %0, %1, %2;" : "=r"(d) : "f"(hi), "f"(lo));
    return d;
}
// dual-gate tanh: one MUFU for two values
__device__ __forceinline__ uint32_t tanh2(uint32_t a) {
    uint32_t d;
    asm("tanh.approx.f16x2 %0, %1;" : "=r"(d) : "r"(a));
    return d;
}
// sigmoid pair from PRE-SCALED args (arg = 0.5*logit): 0.5*tanh(arg)+0.5
__device__ __forceinline__ float2 sigm2_s(float a0, float a1) {
    const __half2 h05 = __floats2half2_rn(0.5f, 0.5f);
    __half2 t = u2h(tanh2(packf2h2(a0, a1)));
    return __half22float2(__hfma2(t, h05, h05));
}

// single-MUFU fp32 transcendentals (MUFU.TANH)
__device__ __forceinline__ float tanhx(float x) {
    float y; asm("tanh.approx.f32 %0, %1;" : "=f"(y) : "f"(x)); return y;
}
// fp32 sigmoid from PRE-SCALED arg (peel path)
__device__ __forceinline__ float sigm_s(float x) {
    return fmaf(0.5f, tanhx(x), 0.5f);
}

// stage Whh (192x64 fp32) as fp16 SW128 tile; r/z gate rows (g < 128)
// prescaled by 0.5 (exact in fp16) so sigmoid args arrive pre-scaled
__device__ __forceinline__ void stage_whh(char* smem, const float* Wc, int tid) {
    for (int idx = tid; idx < GG * HH; idx += BT) {
        int g = idx >> 6, k = idx & 63;
        float w = Wc[idx];
        if (g < 128) w *= 0.5f;
        uint32_t off = (uint32_t)g * 128u + (uint32_t)k * 2u;
        uint32_t sw = off ^ ((off >> 3) & 0x70);
        *(__half*)(smem + W_T + sw) = __float2half_rn(w);
    }
}

// load B tiles for chunk ch; 24 main HMMA + 4 augmented (r/z gi fold)
__device__ __forceinline__ void issue_chunk(uint32_t sb, uint32_t bRow,
                                            uint32_t bk0, uint32_t bk1,
                                            uint32_t w2b,
                                            const uint32_t (&Ah)[2][4][4],
                                            const uint32_t (&A2f)[2][4],
                                            float (*acc)[2][4], int ch,
                                            const float (&zq)[4]) {
    uint32_t B0[3][8];
    #pragma unroll
    for (int g = 0; g < 3; g++) {
        uint32_t wb = sb + W_T + (uint32_t)(g*64 + ch*8) * 128u + bRow;
        ldsm4(&B0[g][0], wb + bk0);
        ldsm4(&B0[g][4], wb + bk1);
    }
    #pragma unroll
    for (int g = 0; g < 3; g++)
        #pragma unroll
        for (int mt = 0; mt < 2; mt++) {
            hmma_zc(acc[g][mt], Ah[mt][0], B0[g][0], B0[g][1], zq);
            #pragma unroll
            for (int kt = 1; kt < 4; kt++) {
                int bi = (kt >> 1) * 4 + (kt & 1) * 2;
                hmma(acc[g][mt], Ah[mt][kt], B0[g][bi], B0[g][bi + 1]);
            }
        }
    // augmented K-tile: adds x-gi + bias to r and z accumulators
    uint32_t br[2], bz[2];
    ldsm2(br, w2b + (uint32_t)(ch * 384));
    ldsm2(bz, w2b + (uint32_t)(ch * 384) + 3072u);
    hmma(acc[0][0], A2f[0], br[0], br[1]);
    hmma(acc[0][1], A2f[1], br[0], br[1]);
    hmma(acc[1][0], A2f[0], bz[0], bz[1]);
    hmma(acc[1][1], A2f[1], bz[0], bz[1]);
}

extern "C" __global__ void __launch_bounds__(BT, 3)
rnn_kernel(const float* __restrict__ X,
           const float* __restrict__ eWih, const float* __restrict__ eWhh,
           const float* __restrict__ ebih, const float* __restrict__ ebhh,
           const float* __restrict__ dWih, const float* __restrict__ dWhh,
           const float* __restrict__ dbih, const float* __restrict__ dbhh,
           const float* __restrict__ linW, const float* __restrict__ linb,
           const float* __restrict__ embed, float* __restrict__ out)
{
    extern __shared__ char smem[];
    const uint32_t sb = smem_u32(smem);
    float* sCst = (float*)(smem + CST_O);
    float* sLin = (float*)(smem + LIN_O);

    const int tid  = threadIdx.x;
    const int lane = tid & 31;
    const int w    = tid >> 5;
    const int l3   = lane & 3;
    const int qr   = lane >> 2;
    const int c    = blockIdx.y;
    const int r    = blockIdx.x * BT + tid;
    const int rr   = (r < BNR) ? r : (BNR - 1);

    // ---- stage encoder weights ----
    stage_whh(smem, eWhh + (size_t)c * GG * HH, tid);
    for (int u = tid; u < HH; u += BT) {
        int base = c * GG;
        sCst[u*12+0]  = 0.5f * eWih[(base + u) * 2 + 0];
        sCst[u*12+1]  = 0.5f * eWih[(base + u) * 2 + 1];
        sCst[u*12+2]  = 0.5f * (ebih[base + u] + ebhh[base + u]);
        sCst[u*12+3]  = 0.0f;
        sCst[u*12+4]  = 0.5f * eWih[(base + 64 + u) * 2 + 0];
        sCst[u*12+5]  = 0.5f * eWih[(base + 64 + u) * 2 + 1];
        sCst[u*12+6]  = 0.5f * (ebih[base + 64 + u] + ebhh[base + 64 + u]);
        sCst[u*12+7]  = 0.0f;
        sCst[u*12+8]  = eWih[(base + 128 + u) * 2 + 0];
        sCst[u*12+9]  = eWih[(base + 128 + u) * 2 + 1];
        sCst[u*12+10] = ebih[base + 128 + u];
        sCst[u*12+11] = ebhh[base + 128 + u];
    }
    for (int i = tid; i < 4096; i += BT) ((uint32_t*)(smem + A_T))[i] = 0u;
    // zero A2 + W2 regions
    for (int i = tid; i < 3072; i += BT) ((uint32_t*)(smem + A2_O))[i] = 0u;
    // RACE FIX: zero-fill must complete before per-element A2/W2 writes
    // (zeroing thread for a given address != writing thread)
    __syncthreads();
    // A2 col2 = 1.0 (multiplies the bias row of W2)
    sts32(sb + A2_O + (uint32_t)tid * 48u + 4u, pack2h(1.0f, 0.0f));
    // W2: r/z rows [0.5wih0, 0.5wih1, 0.5(bih+bhh)]
    {
        int g = tid >> 6, u = tid & 63, base = c * GG;
        float w0 = 0.5f * eWih[(base + g*64 + u) * 2 + 0];
        float w1 = 0.5f * eWih[(base + g*64 + u) * 2 + 1];
        float bs = 0.5f * (ebih[base + g*64 + u] + ebhh[base + g*64 + u]);
        sts32(sb + W2_O + (uint32_t)tid * 48u,      pack2h(w0, w1));
        sts32(sb + W2_O + (uint32_t)tid * 48u + 4u, pack2h(bs, 0.0f));
    }
    __syncthreads();

    // ---- per-lane address constants ----
    const int rb = lane & 15;
    const uint32_t aBase0 = sb + A_T + (uint32_t)(w*32 + rb) * 128u;
    const uint32_t aBase1 = aBase0 + 16u*128u;
    const uint32_t akh  = ((uint32_t)lane >> 4) * 16u;
    const uint32_t axor = ((uint32_t)(rb & 7)) << 4;
    uint32_t akoff[4];
    #pragma unroll
    for (int kt = 0; kt < 4; kt++) akoff[kt] = ((uint32_t)kt*32u + akh) ^ axor;

    const uint32_t bg    = lane & 7;
    const uint32_t bkoff = ((uint32_t)lane >> 3) * 16u;
    const uint32_t bxor  = bg << 4;
    const uint32_t bk0 = (0u  + bkoff) ^ bxor;
    const uint32_t bk1 = (64u + bkoff) ^ bxor;
    const uint32_t bRow = bg * 128u;

    // augmented-tile lane addresses (48B row stride, no swizzle needed)
    const uint32_t a2Base = sb + A2_O + (uint32_t)(w*32 + rb) * 48u + akh;
    const uint32_t w2b = sb + W2_O + (uint32_t)(lane & 7) * 48u
                       + (((uint32_t)(lane >> 3) & 1u) * 16u);

    // fragment-row constants: rows i=0..3 -> warp-local row qr + {0,8,16,24}
    uint32_t hbase[4], hsw[4], xaddr[4], a2row[4];
    int growG[4];
    float wq[4];   // softmax(embed[n])[c] for my rows (fused mix weight)
    #pragma unroll
    for (int i = 0; i < 4; i++) {
        int grow = w*32 + (i>>1)*16 + (i&1)*8 + qr;
        growG[i] = blockIdx.x * BT + grow;
        hbase[i] = sb + A_T + (uint32_t)grow * 128u;
        hsw[i]   = ((uint32_t)(grow & 7)) << 4;
        xaddr[i] = sb + X_O + (uint32_t)grow * 8u;
        a2row[i] = sb + A2_O + (uint32_t)grow * 48u;
        int gg = (growG[i] < BNR) ? growG[i] : 0;
        const float* e = embed + (gg % NN) * CC;
        float m = e[0];
        #pragma unroll
        for (int cc = 1; cc < CC; cc++) m = fmaxf(m, e[cc]);
        float s = 0.0f;
        #pragma unroll
        for (int cc = 0; cc < CC; cc++) s += __expf(e[cc] - m);
        wq[i] = __fdividef(__expf(e[c] - m), s);
    }
    const uint32_t colb = (uint32_t)(l3 * 4);       // byte offset of unit pair in row
    const uint32_t cstb = sb + CST_O + (uint32_t)(l3 * 2) * 48u;  // + ch*8*48
    const uint32_t linb_a = sb + LIN_O + (uint32_t)(l3 * 2) * 4u;

    const float* xr = X + (size_t)rr * (TT * 2);
    float lb = 0.0f;
    float lastx0 = 0.0f;

    // zero quad for first-k HMMA C operand
    float zq[4] = {0.0f, 0.0f, 0.0f, 0.0f};

    // ---- peeled step t=0: h = 0 -> gh = 0, no MMA at all ----
    {
        float2 xv0 = *(const float2*)(xr);
        sts64f(sb + X_O + (uint32_t)tid * 8u, xv0.x, xv0.y);
        __syncwarp();
        float x0[4], x1[4];
        #pragma unroll
        for (int i = 0; i < 4; i++) {
            float2 xv = lds64f(xaddr[i]);
            x0[i] = xv.x; x1[i] = xv.y;
        }
        #pragma unroll
        for (int ch = 0; ch < 8; ch++) {
            uint32_t cb = cstb + (uint32_t)(ch * 8) * 48u;
            float4 cr0 = lds128f(cb);       float4 cz0 = lds128f(cb + 16);
            float4 cn0 = lds128f(cb + 32);
            float4 cr1 = lds128f(cb + 48);  float4 cz1 = lds128f(cb + 64);
            float4 cn1 = lds128f(cb + 80);
            uint32_t choff = (uint32_t)(ch * 16) + colb;
            #pragma unroll
            for (int i = 0; i < 4; i++) {
                float rg0 = sigm_s(fmaf(cr0.x, x0[i], fmaf(cr0.y, x1[i], cr0.z)));
                float zg0 = sigm_s(fmaf(cz0.x, x0[i], fmaf(cz0.y, x1[i], cz0.z)));
                float gi0 = fmaf(cn0.x, x0[i], fmaf(cn0.y, x1[i], cn0.z));
                float ng0 = tanhx(fmaf(rg0, cn0.w, gi0));
                float hn0 = fmaf(zg0, -ng0, ng0);          // h_old = 0

                float rg1 = sigm_s(fmaf(cr1.x, x0[i], fmaf(cr1.y, x1[i], cr1.z)));
                float zg1 = sigm_s(fmaf(cz1.x, x0[i], fmaf(cz1.y, x1[i], cz1.z)));
                float gi1 = fmaf(cn1.x, x0[i], fmaf(cn1.y, x1[i], cn1.z));
                float ng1 = tanhx(fmaf(rg1, cn1.w, gi1));
                float hn1 = fmaf(zg1, -ng1, ng1);

                sts32(hbase[i] + (choff ^ hsw[i]), pack2h(hn0, hn1));
            }
        }
    }

    // ---- main loop t = 1 .. 23 ----
    #pragma unroll 1
    for (int t = 1; t < 2 * TT; t++) {
        if (t == TT) {   // restage decoder weights
            __syncthreads();
            stage_whh(smem, dWhh + (size_t)c * GG * HH, tid);
            for (int u = tid; u < HH; u += BT) {
                int base = c * GG;
                sCst[u*12+8]  = dWih[base + 128 + u];
                sCst[u*12+9]  = 0.0f;
                sCst[u*12+10] = dbih[base + 128 + u];
                sCst[u*12+11] = dbhh[base + 128 + u];
            }
            {   // W2 decoder: [0.5*dWih, 0, 0.5*(dbih+dbhh)]
                int g = tid >> 6, u = tid & 63, base = c * GG;
                float w0 = 0.5f * dWih[base + g*64 + u];
                float bs = 0.5f * (dbih[base + g*64 + u] + dbhh[base + g*64 + u]);
                sts32(sb + W2_O + (uint32_t)tid * 48u,      pack2h(w0, 0.0f));
                sts32(sb + W2_O + (uint32_t)tid * 48u + 4u, pack2h(bs, 0.0f));
            }
            // A2 for decoder step t=TT: x = (last x0, 0)
            sts32(sb + A2_O + (uint32_t)tid * 48u, pack2h(lastx0, 0.0f));
            for (int k = tid; k < HH; k += BT) sLin[k] = linW[c*HH + k];
            __syncthreads();
            lb = linb[c];
        }

        if (t < TT) {    // stage this step's input (own row -> own warp region)
            float2 xv = *(const float2*)(xr + 2*t);
            sts64f(sb + X_O + (uint32_t)tid * 8u, xv.x, xv.y);
            sts32(sb + A2_O + (uint32_t)tid * 48u, pack2h(xv.x, xv.y));
            lastx0 = xv.x;
        }
        __syncwarp();    // prev-step hn/A2/X stores + staging visible

        // load this warp's A fragments (h fp16) + augmented x fragment
        uint32_t Ah[2][4][4], A2f[2][4];
        #pragma unroll
        for (int kt = 0; kt < 4; kt++) {
            ldsm4(Ah[0][kt], aBase0 + akoff[kt]);
            ldsm4(Ah[1][kt], aBase1 + akoff[kt]);
        }
        ldsm4(A2f[0], a2Base);
        ldsm4(A2f[1], a2Base + 768u);

        // per-row inputs (n-gate gi path)
        float x0[4], x1[4], v[4];
        #pragma unroll
        for (int i = 0; i < 4; i++) {
            float2 xv = lds64f(xaddr[i]);
            x0[i] = xv.x;
            x1[i] = (t < TT) ? xv.y : 0.0f;
            v[i] = 0.0f;
        }

        // ---- software-pipelined chunk loop ----
        float accbuf[2][3][2][4];
        issue_chunk(sb, bRow, bk0, bk1, w2b, Ah, A2f, accbuf[0], 0, zq);

        #pragma unroll
        for (int ch = 0; ch < 8; ch++) {
            if (ch < 7)
                issue_chunk(sb, bRow, bk0, bk1, w2b, Ah, A2f,
                            accbuf[(ch + 1) & 1], ch + 1, zq);
            float (*acc)[2][4] = accbuf[ch & 1];

            // per-unit-pair constants: n gate only (r/z fully folded into MMA)
            uint32_t cb = cstb + (uint32_t)(ch * 8) * 48u;
            float4 cn0 = lds128f(cb + 32);
            float4 cn1 = lds128f(cb + 80);
            float2 lw  = lds64f(linb_a + (uint32_t)(ch * 32));

            uint32_t choff = (uint32_t)(ch * 16) + colb;

            #pragma unroll
            for (int i = 0; i < 4; i++) {
                const int mt = i >> 1, p = i & 1;
                float gn0 = acc[2][mt][2*p],   gn1 = acc[2][mt][2*p+1];

                uint32_t haddr = hbase[i] + (choff ^ hsw[i]);
                uint32_t hraw = lds32(haddr);
                float2 ho = __half22float2(*(__half2*)&hraw);

                // r/z: accumulators ARE the pre-scaled sigmoid args
                float2 rgf = sigm2_s(acc[0][mt][2*p], acc[0][mt][2*p+1]);
                float2 zgf = sigm2_s(acc[1][mt][2*p], acc[1][mt][2*p+1]);

                float gi0 = fmaf(cn0.x, x0[i], fmaf(cn0.y, x1[i], cn0.z));
                float ng0 = tanhx(fmaf(rgf.x, gn0 + cn0.w, gi0));
                float hn0 = fmaf(zgf.x, ho.x - ng0, ng0);

                float gi1 = fmaf(cn1.x, x0[i], fmaf(cn1.y, x1[i], cn1.z));
                float ng1 = tanhx(fmaf(rgf.y, gn1 + cn1.w, gi1));
                float hn1 = fmaf(zgf.y, ho.y - ng1, ng1);

                sts32(haddr, pack2h(hn0, hn1));

                if (t >= TT)
                    v[i] = fmaf(hn0, lw.x, fmaf(hn1, lw.y, v[i]));
            }
        }

        if (t >= TT) {   // decoder: reduce lin projection, mix-fused output, feed back
            const int td = t - TT;
            #pragma unroll
            for (int i = 0; i < 4; i++) {
                v[i] += __shfl_xor_sync(0xFFFFFFFFu, v[i], 1);
                v[i] += __shfl_xor_sync(0xFFFFFFFFu, v[i], 2);
            }
            if (l3 == 0) {
                #pragma unroll
                for (int i = 0; i < 4; i++) {
                    float val = v[i] + lb;
                    if (growG[i] < BNR)
                        atomicAdd(out + growG[i] * TT + td, wq[i] * val);
                    sts64f(xaddr[i], val, 0.0f);
                    sts32(a2row[i], pack2h(val, 0.0f));
                }
            }
        }
    }
}

// zero the output (harness poisons it to 0xAA; atomics accumulate into it)
extern "C" __global__ void zero_kernel(float* __restrict__ out)
{
    int i = blockIdx.x * blockDim.x + threadIdx.x;
    if (i < NOUT) out[i] = 0.0f;
}

extern "C" void kernel_launch(void* const* d_in, const int* in_sizes, int n_in,
                              void* d_out, int out_size)
{
    // metadata order: A, X, enc_Wih, enc_Whh, enc_bih, enc_bhh,
    //                 dec_Wih, dec_Whh, dec_bih, dec_bhh, lin_W, lin_b, embed
    const float* X     = (const float*)d_in[1];
    const float* eWih  = (const float*)d_in[2];
    const float* eWhh  = (const float*)d_in[3];
    const float* ebih  = (const float*)d_in[4];
    const float* ebhh  = (const float*)d_in[5];
    const float* dWih  = (const float*)d_in[6];
    const float* dWhh  = (const float*)d_in[7];
    const float* dbih  = (const float*)d_in[8];
    const float* dbhh  = (const float*)d_in[9];
    const float* linW  = (const float*)d_in[10];
    const float* linb  = (const float*)d_in[11];
    const float* embed = (const float*)d_in[12];
    float* out = (float*)d_out;

    cudaFuncSetAttribute((const void*)rnn_kernel,
                         cudaFuncAttributeMaxDynamicSharedMemorySize, SMEM_BYTES);

    zero_kernel<<<(NOUT + 255) / 256, 256>>>(out);

    dim3 grid((BNR + BT - 1) / BT, CC);   // (82, 10)
    rnn_kernel<<<grid, BT, SMEM_BYTES>>>(X, eWih, eWhh, ebih, ebhh,
                                         dWih, dWhh, dbih, dbhh, linW, linb,
                                         embed, out);
}